// round 16
// baseline (speedup 1.0000x reference)
#include <cuda_runtime.h>
#include <cuda_bf16.h>
#include <cuda_fp16.h>
#include <math.h>
#include <stdint.h>

// Problem constants
#define BB 512
#define KK 256
#define NN 512
#define CC 6
#define J4 (KK/4)       // 64 groups of 4 k's
#define HALF_N 256      // tracks per block (2 blocks per batch)
#define TPB 128         // threads per block; each thread owns 2 tracks

#define LOG2E_F 1.4426950408889634f
#define LN2_F   0.6931471805599453f
#define LOG2PI_LOG2E_F 2.6514961294723187f  // log2(2*pi)
#define RQ2_F 0.72134752044448170f          // 0.5 * log2(e)

// ---------------- scratch (static device globals; no allocation) -------------
__device__ double4 g_part[2 * BB];           // {spatial, efs, cnt, lam} per block
__device__ unsigned int g_done = 0;

// ---------------- fast math helpers ------------------------------------------
__device__ __forceinline__ float ex2f(float x) {
    float y; asm("ex2.approx.ftz.f32 %0, %1;" : "=f"(y) : "f"(x)); return y;
}
__device__ __forceinline__ float lg2f(float x) {
    float y; asm("lg2.approx.ftz.f32 %0, %1;" : "=f"(y) : "f"(x)); return y;
}
// dual-half exp2: one MUFU op computes 2^x for both halves
__device__ __forceinline__ __half2 h2ex2(__half2 x) {
    uint32_t xi = *reinterpret_cast<uint32_t*>(&x), yi;
    asm("ex2.approx.f16x2 %0, %1;" : "=r"(yi) : "r"(xi));
    return *reinterpret_cast<__half2*>(&yi);
}
__device__ __forceinline__ __half2 u2h2(uint32_t u) {
    return *reinterpret_cast<__half2*>(&u);
}
__device__ __forceinline__ double warpRedD(double v) {
    #pragma unroll
    for (int o = 16; o; o >>= 1) v += __shfl_down_sync(0xffffffffu, v, o);
    return v;
}

// Compute 4 q's for one track from one 4-k coefficient group.
__device__ __forceinline__ void q4(
    const float4& a0, const float4& a1, const float4& a2, const float4& a3,
    const float4& cA, const float4& cB, float x, float y,
    float& q0, float& q1, float& q2, float& q3)
{
    // Horner: q = c0 + (c1 + c3*x)*x + (c2 + c5*x + c4*y)*y
    float u1 = fmaf(a0.w, x, a0.y);
    float u2 = fmaf(cA.y, x, a0.z);
    u2 = fmaf(cA.x, y, u2);
    q0 = fmaf(u1, x, a0.x);
    q0 = fmaf(u2, y, q0);

    float v1 = fmaf(a1.w, x, a1.y);
    float v2 = fmaf(cA.w, x, a1.z);
    v2 = fmaf(cA.z, y, v2);
    q1 = fmaf(v1, x, a1.x);
    q1 = fmaf(v2, y, q1);

    float w1 = fmaf(a2.w, x, a2.y);
    float w2 = fmaf(cB.y, x, a2.z);
    w2 = fmaf(cB.x, y, w2);
    q2 = fmaf(w1, x, a2.x);
    q2 = fmaf(w2, y, q2);

    float z1 = fmaf(a3.w, x, a3.y);
    float z2 = fmaf(cB.w, x, a3.z);
    z2 = fmaf(cB.z, y, z2);
    q3 = fmaf(z1, x, a3.x);
    q3 = fmaf(z2, y, q3);
}

// ---------------- main kernel (fully fused) -----------------------------------
__global__ __launch_bounds__(TPB) void main_kernel(
    const float* __restrict__ pi,
    const float* __restrict__ mu,
    const float* __restrict__ L,
    const float* __restrict__ ef_logits,
    const float* __restrict__ tracks,
    const uint32_t* __restrict__ mask,
    float* __restrict__ out)
{
    const int bid  = blockIdx.x;
    const int b    = bid >> 1;
    const int half = bid & 1;
    const int tid  = threadIdx.x;

    __shared__ float4 scA[KK];           // {c0,c1,c2,c3} per k          4 KB
    __shared__ float4 scC[2 * J4];       // {c4,c5} pairs per 4-k group  2 KB
    __shared__ uint2  sce4[J4 * CC];     // half4 ce per (j2, g)         3 KB
    __shared__ double red[4 * 4];
    __shared__ bool   isLast;

    // Lambda contribution: only half 0 accumulates pi (each thread covers 2 k's)
    double lam = 0.0;
    if (half == 0) {
        lam = (double)pi[(size_t)b * KK + tid] + (double)pi[(size_t)b * KK + tid + TPB];
    }

    const int n0 = half * HALF_N;
    // prefix-mask property: first inactive => whole 256-track range inactive
    const bool blockActive = (mask[(size_t)b * NN + n0] != 0u);

    double spatial = 0.0, efs = 0.0, cnt = 0.0;

    if (blockActive) {
        // ---- staging (float): thread tid builds coefficients for k=tid, tid+128 ----
        #pragma unroll
        for (int kk = 0; kk < 2; kk++) {
            const int k = tid + kk * TPB;
            const int i = b * KK + k;
            float pv = pi[i];
            float a  = L[i * 4 + 0];
            float bb = L[i * 4 + 2];
            float c  = L[i * 4 + 3];
            float m0 = mu[i * 2 + 0];
            float m1 = mu[i * 2 + 1];

            float base2 = lg2f(pv) - LOG2PI_LOG2E_F - lg2f(a * c);  // < 0

            float A2  = RQ2_F / (a * a);
            float Cr2 = RQ2_F / (c * c);
            float BA  = bb / a;
            float P = fmaf(Cr2 * BA, BA, A2);
            float Q = Cr2;
            float R = -2.0f * Cr2 * BA;

            float4 v4;
            v4.x = base2 - P * m0 * m0 - Q * m1 * m1 - R * m0 * m1;
            v4.y = fmaf(2.0f * P, m0, R * m1);
            v4.z = fmaf(2.0f * Q, m1, R * m0);
            v4.w = -P;
            scA[k] = v4;

            const int j2 = k >> 2, slot = k & 3;
            float* fC = (float*)scC;
            fC[j2 * 8 + slot * 2 + 0] = -Q;
            fC[j2 * 8 + slot * 2 + 1] = -R;

            // CE table: lse(ef_logits) - ef_logits[c], half4 per (j2,g) layout
            float e[CC];
            float mx = -INFINITY;
            #pragma unroll
            for (int c2 = 0; c2 < CC; c2++) {
                e[c2] = ef_logits[(size_t)i * CC + c2];
                mx = fmaxf(mx, e[c2]);
            }
            float ssum = 0.f;
            #pragma unroll
            for (int c2 = 0; c2 < CC; c2++) ssum += ex2f((e[c2] - mx) * LOG2E_F);
            float lse = mx + lg2f(ssum) * LN2_F;
            __half* hce = reinterpret_cast<__half*>(sce4);
            #pragma unroll
            for (int c2 = 0; c2 < CC; c2++)
                hce[(j2 * CC + c2) * 4 + slot] = __float2half_rn(lse - e[c2]);
        }
        __syncthreads();

        // ---- per-track pass: thread owns tracks n0+tid (A) and n0+tid+128 (B) ----
        const int nA = n0 + tid;
        const int nB = nA + TPB;
        const bool actA = (mask[(size_t)b * NN + nA] != 0u);
        const bool actB = (mask[(size_t)b * NN + nB] != 0u);
        const bool anyA = (__ballot_sync(0xffffffffu, actA) != 0u);
        const bool anyB = (__ballot_sync(0xffffffffu, actB) != 0u);

        if (anyA) {
            const float* trA = tracks + ((size_t)b * NN + nA) * 6;
            const float* trB = tracks + ((size_t)b * NN + nB) * 6;
            float x0A = trA[0], x1A = trA[1];
            int   gA  = (int)trA[5];
            const uint2* cepA = sce4 + gA;

            float sA = 0.f, tA = 0.f;
            const __half2 hz = __floats2half2_rn(0.f, 0.f);

            if (anyB) {
                float x0B = trB[0], x1B = trB[1];
                int   gB  = (int)trB[5];
                const uint2* cepB = sce4 + gB;
                float sB = 0.f, tB = 0.f;

                for (int J = 0; J < J4; J += 8) {
                    __half2 sAh = hz, tAh = hz, sBh = hz, tBh = hz;
                    #pragma unroll 2
                    for (int j2 = J; j2 < J + 8; j2++) {
                        const float4 a0 = scA[4 * j2 + 0];
                        const float4 a1 = scA[4 * j2 + 1];
                        const float4 a2 = scA[4 * j2 + 2];
                        const float4 a3 = scA[4 * j2 + 3];
                        const float4 cA = scC[2 * j2 + 0];
                        const float4 cB = scC[2 * j2 + 1];
                        const uint2 ceA = cepA[j2 * CC];
                        const uint2 ceB = cepB[j2 * CC];

                        float qA0, qA1, qA2, qA3, qB0, qB1, qB2, qB3;
                        q4(a0, a1, a2, a3, cA, cB, x0A, x1A, qA0, qA1, qA2, qA3);
                        q4(a0, a1, a2, a3, cA, cB, x0B, x1B, qB0, qB1, qB2, qB3);

                        __half2 pA01 = h2ex2(__floats2half2_rn(qA0, qA1));
                        __half2 pA23 = h2ex2(__floats2half2_rn(qA2, qA3));
                        __half2 pB01 = h2ex2(__floats2half2_rn(qB0, qB1));
                        __half2 pB23 = h2ex2(__floats2half2_rn(qB2, qB3));

                        sAh = __hadd2(sAh, pA01);
                        sAh = __hadd2(sAh, pA23);
                        sBh = __hadd2(sBh, pB01);
                        sBh = __hadd2(sBh, pB23);
                        tAh = __hfma2(pA01, u2h2(ceA.x), tAh);
                        tAh = __hfma2(pA23, u2h2(ceA.y), tAh);
                        tBh = __hfma2(pB01, u2h2(ceB.x), tBh);
                        tBh = __hfma2(pB23, u2h2(ceB.y), tBh);
                    }
                    float2 f;
                    f = __half22float2(sAh); sA += f.x + f.y;
                    f = __half22float2(tAh); tA += f.x + f.y;
                    f = __half22float2(sBh); sB += f.x + f.y;
                    f = __half22float2(tBh); tB += f.x + f.y;
                }
                if (actB) {
                    spatial -= (double)(lg2f(sB) * LN2_F);
                    efs     += (double)(tB / sB);
                    cnt     += 1.0;
                }
            } else {
                for (int J = 0; J < J4; J += 8) {
                    __half2 sAh = hz, tAh = hz;
                    #pragma unroll 2
                    for (int j2 = J; j2 < J + 8; j2++) {
                        const float4 a0 = scA[4 * j2 + 0];
                        const float4 a1 = scA[4 * j2 + 1];
                        const float4 a2 = scA[4 * j2 + 2];
                        const float4 a3 = scA[4 * j2 + 3];
                        const float4 cA = scC[2 * j2 + 0];
                        const float4 cB = scC[2 * j2 + 1];
                        const uint2 ceA = cepA[j2 * CC];

                        float qA0, qA1, qA2, qA3;
                        q4(a0, a1, a2, a3, cA, cB, x0A, x1A, qA0, qA1, qA2, qA3);

                        __half2 pA01 = h2ex2(__floats2half2_rn(qA0, qA1));
                        __half2 pA23 = h2ex2(__floats2half2_rn(qA2, qA3));

                        sAh = __hadd2(sAh, pA01);
                        sAh = __hadd2(sAh, pA23);
                        tAh = __hfma2(pA01, u2h2(ceA.x), tAh);
                        tAh = __hfma2(pA23, u2h2(ceA.y), tAh);
                    }
                    float2 f;
                    f = __half22float2(sAh); sA += f.x + f.y;
                    f = __half22float2(tAh); tA += f.x + f.y;
                }
            }
            if (actA) {
                spatial -= (double)(lg2f(sA) * LN2_F);
                efs     += (double)(tA / sA);
                cnt     += 1.0;
            }
        }
    }

    // ---- block reduce 4 doubles (uniform control, 4 warps) ----
    spatial = warpRedD(spatial);
    efs     = warpRedD(efs);
    cnt     = warpRedD(cnt);
    lam     = warpRedD(lam);
    const int wid = tid >> 5, lid = tid & 31;
    if (lid == 0) {
        red[wid]      = spatial;
        red[4 + wid]  = efs;
        red[8 + wid]  = cnt;
        red[12 + wid] = lam;
    }
    __syncthreads();
    if (tid == 0) {
        double s0 = 0, s1 = 0, s2 = 0, s3 = 0;
        #pragma unroll
        for (int w = 0; w < 4; w++) {
            s0 += red[w]; s1 += red[4 + w]; s2 += red[8 + w]; s3 += red[12 + w];
        }
        g_part[bid] = make_double4(s0, s1, s2, s3);
    }

    // ---- last-block-done finalize (deterministic fixed-order sum) ----
    __threadfence();
    if (tid == 0) {
        unsigned int v = atomicAdd(&g_done, 1u);
        isLast = (v == 2u * BB - 1u);
    }
    __syncthreads();
    if (isLast) {
        double lamSum = 0, cntSum = 0, l1Sum = 0, spSum = 0, efSum = 0;
        for (int b2 = tid; b2 < BB; b2 += TPB) {
            double4 e0 = g_part[2 * b2];
            double4 e1 = g_part[2 * b2 + 1];
            double sp = e0.x + e1.x;
            double ef = e0.y + e1.y;
            double gc = e0.z + e1.z;
            double lm = e0.w + e1.w;
            lamSum += lm;
            cntSum += gc;
            l1Sum  += fabs(lm - gc) * sqrt(gc + 1.0);
            spSum  += sp;
            efSum  += ef;
        }
        lamSum = warpRedD(lamSum);
        cntSum = warpRedD(cntSum);
        l1Sum  = warpRedD(l1Sum);
        spSum  = warpRedD(spSum);
        efSum  = warpRedD(efSum);
        __syncthreads();
        __shared__ double red5[4 * 5];
        if (lid == 0) {
            red5[wid]      = lamSum;
            red5[4 + wid]  = cntSum;
            red5[8 + wid]  = l1Sum;
            red5[12 + wid] = spSum;
            red5[16 + wid] = efSum;
        }
        __syncthreads();
        if (tid == 0) {
            double a0 = 0, a1 = 0, a2 = 0, a3 = 0, a4 = 0;
            #pragma unroll
            for (int w = 0; w < 4; w++) {
                a0 += red5[w]; a1 += red5[4 + w]; a2 += red5[8 + w];
                a3 += red5[12 + w]; a4 += red5[16 + w];
            }
            double count_loss = a0 / (double)BB;
            double n_total    = a1 > 1.0 ? a1 : 1.0;
            double count_l1   = a2 / (double)BB;
            double spatialL   = a3 / n_total;
            double efL        = a4 / n_total;
            double total = count_loss + spatialL + efL + count_l1;
            out[0] = (float)total;
            out[1] = (float)spatialL;
            out[2] = (float)count_loss;
            out[3] = (float)count_l1;
            out[4] = (float)efL;
            g_done = 0;  // reset for next graph replay
        }
    }
}

// ---------------- launch -------------------------------------------------------
extern "C" void kernel_launch(void* const* d_in, const int* in_sizes, int n_in,
                              void* d_out, int out_size) {
    const float* pi        = (const float*)d_in[0];
    const float* mu        = (const float*)d_in[1];
    const float* L         = (const float*)d_in[2];
    const float* ef_logits = (const float*)d_in[3];
    const float* tracks    = (const float*)d_in[4];
    const uint32_t* mask   = (const uint32_t*)d_in[5];

    main_kernel<<<2 * BB, TPB>>>(pi, mu, L, ef_logits, tracks, mask, (float*)d_out);
}

// round 17
// speedup vs baseline: 1.1734x; 1.1734x over previous
#include <cuda_runtime.h>
#include <cuda_bf16.h>
#include <cuda_fp16.h>
#include <math.h>
#include <stdint.h>

// Problem constants
#define BB 512
#define KK 256
#define NN 512
#define CC 6
#define J4 (KK/4)       // 64 quads of k
#define HALF_N 256      // tracks per block (2 blocks per batch)
#define TPB 128         // threads per block; each thread owns 2 tracks

#define LOG2E_F 1.4426950408889634f
#define LN2_F   0.6931471805599453f
#define LOG2PI_LOG2E_F 2.6514961294723187f  // log2(2*pi)
#define RQ2_F 0.72134752044448170f          // 0.5 * log2(e)

// ---------------- scratch (static device globals; no allocation) -------------
__device__ double4 g_part[2 * BB];           // {spatial, efs, cnt, lam} per block
__device__ unsigned int g_done = 0;

// ---------------- fast math helpers ------------------------------------------
__device__ __forceinline__ float ex2f(float x) {
    float y; asm("ex2.approx.ftz.f32 %0, %1;" : "=f"(y) : "f"(x)); return y;
}
__device__ __forceinline__ float lg2f(float x) {
    float y; asm("lg2.approx.ftz.f32 %0, %1;" : "=f"(y) : "f"(x)); return y;
}
// dual-half exp2: one MUFU op computes 2^x for both halves
__device__ __forceinline__ __half2 h2ex2(__half2 x) {
    uint32_t xi = *reinterpret_cast<uint32_t*>(&x), yi;
    asm("ex2.approx.f16x2 %0, %1;" : "=r"(yi) : "r"(xi));
    return *reinterpret_cast<__half2*>(&yi);
}
__device__ __forceinline__ __half2 u2h2(uint32_t u) {
    return *reinterpret_cast<__half2*>(&u);
}
__device__ __forceinline__ double warpRedD(double v) {
    #pragma unroll
    for (int o = 16; o; o >>= 1) v += __shfl_down_sync(0xffffffffu, v, o);
    return v;
}

// q for a k-pair (half2 lanes = 2 k's) in fp16 distance form:
//   q = b2 - P*d0^2 - Q*d1^2 - R*d0*d1,  d = x - mu
// c1 = {m0p, m1p, nPp, nQp} as 4 half2; c2 = {nRp, b2p} as 2 half2
__device__ __forceinline__ __half2 qpair(
    const uint4& c1, const uint2& c2, __half2 xh, __half2 yh)
{
    __half2 d0 = __hsub2(xh, u2h2(c1.x));
    __half2 d1 = __hsub2(yh, u2h2(c1.y));
    __half2 w1 = __hmul2(u2h2(c1.z), d0);
    w1 = __hfma2(u2h2(c2.x), d1, w1);          // -P*d0 - R*d1
    __half2 w2 = __hmul2(u2h2(c1.w), d1);      // -Q*d1
    __half2 q  = __hfma2(w1, d0, u2h2(c2.y));
    return __hfma2(w2, d1, q);
}

// ---------------- main kernel (fully fused) -----------------------------------
__global__ __launch_bounds__(TPB) void main_kernel(
    const float* __restrict__ pi,
    const float* __restrict__ mu,
    const float* __restrict__ L,
    const float* __restrict__ ef_logits,
    const float* __restrict__ tracks,
    const uint32_t* __restrict__ mask,
    float* __restrict__ out)
{
    const int bid  = blockIdx.x;
    const int b    = bid >> 1;
    const int half = bid & 1;
    const int tid  = threadIdx.x;

    __shared__ uint4 sck1[KK / 2];       // per k-pair {m0p,m1p,nPp,nQp}  2 KB
    __shared__ uint2 sck2[KK / 2];       // per k-pair {nRp,b2p}          1 KB
    __shared__ uint2 sce4[J4 * CC];      // half4 ce per (j2, g)          3 KB
    __shared__ double red[4 * 4];
    __shared__ bool   isLast;

    // Lambda contribution: only half 0 accumulates pi (each thread covers 2 k's)
    double lam = 0.0;
    if (half == 0) {
        lam = (double)pi[(size_t)b * KK + tid] + (double)pi[(size_t)b * KK + tid + TPB];
    }

    const int n0 = half * HALF_N;
    // prefix-mask property: first inactive => whole 256-track range inactive
    const bool blockActive = (mask[(size_t)b * NN + n0] != 0u);

    double spatial = 0.0, efs = 0.0, cnt = 0.0;

    if (blockActive) {
        // ---- staging: thread tid builds fp16 coefficients for k=tid, tid+128 ----
        #pragma unroll
        for (int kk = 0; kk < 2; kk++) {
            const int k = tid + kk * TPB;
            const int i = b * KK + k;
            float pv = pi[i];
            float a  = L[i * 4 + 0];
            float bb = L[i * 4 + 2];
            float c  = L[i * 4 + 3];
            float m0 = mu[i * 2 + 0];
            float m1 = mu[i * 2 + 1];

            float base2 = lg2f(pv) - LOG2PI_LOG2E_F - lg2f(a * c);  // < 0

            float A2  = RQ2_F / (a * a);
            float Cr2 = RQ2_F / (c * c);
            float BA  = bb / a;
            float P = fmaf(Cr2 * BA, BA, A2);
            float Q = Cr2;
            float R = -2.0f * Cr2 * BA;

            // fp16 coefficient packing: pair layout (j = k>>1, lane = k&1)
            const int j = k >> 1, lane = k & 1;
            __half* h1 = reinterpret_cast<__half*>(sck1);
            h1[j * 8 + 0 + lane] = __float2half_rn(m0);
            h1[j * 8 + 2 + lane] = __float2half_rn(m1);
            h1[j * 8 + 4 + lane] = __float2half_rn(-P);
            h1[j * 8 + 6 + lane] = __float2half_rn(-Q);
            __half* h2 = reinterpret_cast<__half*>(sck2);
            h2[j * 4 + 0 + lane] = __float2half_rn(-R);
            h2[j * 4 + 2 + lane] = __float2half_rn(base2);

            // CE table: lse(ef_logits) - ef_logits[c], half4 per (j2,g)
            float e[CC];
            float mx = -INFINITY;
            #pragma unroll
            for (int c2 = 0; c2 < CC; c2++) {
                e[c2] = ef_logits[(size_t)i * CC + c2];
                mx = fmaxf(mx, e[c2]);
            }
            float ssum = 0.f;
            #pragma unroll
            for (int c2 = 0; c2 < CC; c2++) ssum += ex2f((e[c2] - mx) * LOG2E_F);
            float lse = mx + lg2f(ssum) * LN2_F;
            const int j2 = k >> 2, slot = k & 3;
            __half* hce = reinterpret_cast<__half*>(sce4);
            #pragma unroll
            for (int c2 = 0; c2 < CC; c2++)
                hce[(j2 * CC + c2) * 4 + slot] = __float2half_rn(lse - e[c2]);
        }
        __syncthreads();

        // ---- per-track pass: thread owns tracks n0+tid (A) and n0+tid+128 (B) ----
        // prefix mask: actB implies actA; anyA false => whole warp range inactive
        const int nA = n0 + tid;
        const int nB = nA + TPB;
        const bool actA = (mask[(size_t)b * NN + nA] != 0u);
        const bool actB = (mask[(size_t)b * NN + nB] != 0u);
        const bool anyA = (__ballot_sync(0xffffffffu, actA) != 0u);

        if (anyA) {
            // tracks memory holds finite values even where masked — safe to compute;
            // B rides in the same half2 lanes at zero marginal cost.
            const float* trA = tracks + ((size_t)b * NN + nA) * 6;
            const float* trB = tracks + ((size_t)b * NN + nB) * 6;
            const __half2 xAh = __half2half2(__float2half_rn(trA[0]));
            const __half2 yAh = __half2half2(__float2half_rn(trA[1]));
            const __half2 xBh = __half2half2(__float2half_rn(trB[0]));
            const __half2 yBh = __half2half2(__float2half_rn(trB[1]));
            const int gA = (int)trA[5];
            const int gB = (int)trB[5];
            const uint2* cepA = sce4 + gA;
            const uint2* cepB = sce4 + gB;

            float sA = 0.f, tA = 0.f, sB = 0.f, tB = 0.f;
            const __half2 hz = __floats2half2_rn(0.f, 0.f);

            for (int J = 0; J < J4; J += 8) {
                __half2 sAh = hz, tAh = hz, sBh = hz, tBh = hz;
                #pragma unroll 2
                for (int j2 = J; j2 < J + 8; j2++) {
                    const uint4 c1a = sck1[2 * j2];
                    const uint2 c2a = sck2[2 * j2];
                    const uint4 c1b = sck1[2 * j2 + 1];
                    const uint2 c2b = sck2[2 * j2 + 1];
                    const uint2 ceA = cepA[j2 * CC];
                    const uint2 ceB = cepB[j2 * CC];

                    // pair 0 (k = 4*j2, 4*j2+1)
                    __half2 pA0 = h2ex2(qpair(c1a, c2a, xAh, yAh));
                    __half2 pB0 = h2ex2(qpair(c1a, c2a, xBh, yBh));
                    // pair 1 (k = 4*j2+2, 4*j2+3)
                    __half2 pA1 = h2ex2(qpair(c1b, c2b, xAh, yAh));
                    __half2 pB1 = h2ex2(qpair(c1b, c2b, xBh, yBh));

                    sAh = __hadd2(sAh, pA0);
                    sAh = __hadd2(sAh, pA1);
                    sBh = __hadd2(sBh, pB0);
                    sBh = __hadd2(sBh, pB1);
                    tAh = __hfma2(pA0, u2h2(ceA.x), tAh);
                    tAh = __hfma2(pA1, u2h2(ceA.y), tAh);
                    tBh = __hfma2(pB0, u2h2(ceB.x), tBh);
                    tBh = __hfma2(pB1, u2h2(ceB.y), tBh);
                }
                float2 f;
                f = __half22float2(sAh); sA += f.x + f.y;
                f = __half22float2(tAh); tA += f.x + f.y;
                f = __half22float2(sBh); sB += f.x + f.y;
                f = __half22float2(tBh); tB += f.x + f.y;
            }
            if (actA) {
                spatial -= (double)(lg2f(sA) * LN2_F);
                efs     += (double)(tA / sA);
                cnt     += 1.0;
            }
            if (actB) {
                spatial -= (double)(lg2f(sB) * LN2_F);
                efs     += (double)(tB / sB);
                cnt     += 1.0;
            }
        }
    }

    // ---- block reduce 4 doubles (uniform control, 4 warps) ----
    spatial = warpRedD(spatial);
    efs     = warpRedD(efs);
    cnt     = warpRedD(cnt);
    lam     = warpRedD(lam);
    const int wid = tid >> 5, lid = tid & 31;
    if (lid == 0) {
        red[wid]      = spatial;
        red[4 + wid]  = efs;
        red[8 + wid]  = cnt;
        red[12 + wid] = lam;
    }
    __syncthreads();
    if (tid == 0) {
        double s0 = 0, s1 = 0, s2 = 0, s3 = 0;
        #pragma unroll
        for (int w = 0; w < 4; w++) {
            s0 += red[w]; s1 += red[4 + w]; s2 += red[8 + w]; s3 += red[12 + w];
        }
        g_part[bid] = make_double4(s0, s1, s2, s3);
    }

    // ---- last-block-done finalize (deterministic fixed-order sum) ----
    __threadfence();
    if (tid == 0) {
        unsigned int v = atomicAdd(&g_done, 1u);
        isLast = (v == 2u * BB - 1u);
    }
    __syncthreads();
    if (isLast) {
        double lamSum = 0, cntSum = 0, l1Sum = 0, spSum = 0, efSum = 0;
        for (int b2 = tid; b2 < BB; b2 += TPB) {
            double4 e0 = g_part[2 * b2];
            double4 e1 = g_part[2 * b2 + 1];
            double sp = e0.x + e1.x;
            double ef = e0.y + e1.y;
            double gc = e0.z + e1.z;
            double lm = e0.w + e1.w;
            lamSum += lm;
            cntSum += gc;
            l1Sum  += fabs(lm - gc) * sqrt(gc + 1.0);
            spSum  += sp;
            efSum  += ef;
        }
        lamSum = warpRedD(lamSum);
        cntSum = warpRedD(cntSum);
        l1Sum  = warpRedD(l1Sum);
        spSum  = warpRedD(spSum);
        efSum  = warpRedD(efSum);
        __syncthreads();
        __shared__ double red5[4 * 5];
        if (lid == 0) {
            red5[wid]      = lamSum;
            red5[4 + wid]  = cntSum;
            red5[8 + wid]  = l1Sum;
            red5[12 + wid] = spSum;
            red5[16 + wid] = efSum;
        }
        __syncthreads();
        if (tid == 0) {
            double a0 = 0, a1 = 0, a2 = 0, a3 = 0, a4 = 0;
            #pragma unroll
            for (int w = 0; w < 4; w++) {
                a0 += red5[w]; a1 += red5[4 + w]; a2 += red5[8 + w];
                a3 += red5[12 + w]; a4 += red5[16 + w];
            }
            double count_loss = a0 / (double)BB;
            double n_total    = a1 > 1.0 ? a1 : 1.0;
            double count_l1   = a2 / (double)BB;
            double spatialL   = a3 / n_total;
            double efL        = a4 / n_total;
            double total = count_loss + spatialL + efL + count_l1;
            out[0] = (float)total;
            out[1] = (float)spatialL;
            out[2] = (float)count_loss;
            out[3] = (float)count_l1;
            out[4] = (float)efL;
            g_done = 0;  // reset for next graph replay
        }
    }
}

// ---------------- launch -------------------------------------------------------
extern "C" void kernel_launch(void* const* d_in, const int* in_sizes, int n_in,
                              void* d_out, int out_size) {
    const float* pi        = (const float*)d_in[0];
    const float* mu        = (const float*)d_in[1];
    const float* L         = (const float*)d_in[2];
    const float* ef_logits = (const float*)d_in[3];
    const float* tracks    = (const float*)d_in[4];
    const uint32_t* mask   = (const uint32_t*)d_in[5];

    main_kernel<<<2 * BB, TPB>>>(pi, mu, L, ef_logits, tracks, mask, (float*)d_out);
}